// round 7
// baseline (speedup 1.0000x reference)
#include <cuda_runtime.h>
#include <cuda_bf16.h>
#include <cstdint>

#define KER 500
#define OO 128
#define BB 8
#define PTOT 16000
#define MT 128              /* patches per CTA tile */
#define NBLK (PTOT/MT)      /* 125 */
#define NCH 64              /* K chunks of 64: K'=4096 */
#define STAGE_BYTES 98304   /* B hi 32K | B lo 32K | A hi 16K | A lo 16K */
#define DSMEM (2*STAGE_BYTES + 1024)

/* B pre-split & pre-swizzled: [chunk][half(hi/lo)][n=256][k=64] bf16 = 4 MB */
__device__ __nv_bfloat16 g_Bs[NCH * 2 * 256 * 64];
__device__ int g_hmax[BB * OO];
__device__ unsigned g_done;

/* ------------------------------------------------------------------ utils */
static __device__ __forceinline__ uint32_t s2u(const void* p) {
    uint32_t r;
    asm("{.reg .u64 t; cvta.to.shared.u64 t, %1; cvt.u32.u64 %0, t;}"
        : "=r"(r) : "l"(p));
    return r;
}
#define SWZ(b) ((b) ^ (((b) >> 3) & 0x70))

static __device__ __forceinline__ void ldsm4(uint32_t* r, uint32_t addr) {
    asm volatile("ldmatrix.sync.aligned.m8n8.x4.shared.b16 {%0,%1,%2,%3}, [%4];"
                 : "=r"(r[0]), "=r"(r[1]), "=r"(r[2]), "=r"(r[3]) : "r"(addr));
}
static __device__ __forceinline__ void mma_bf16(float* d, const uint32_t* a,
                                                uint32_t b0, uint32_t b1) {
    asm volatile(
        "mma.sync.aligned.m16n8k16.row.col.f32.bf16.bf16.f32 "
        "{%0,%1,%2,%3}, {%4,%5,%6,%7}, {%8,%9}, {%0,%1,%2,%3};"
        : "+f"(d[0]), "+f"(d[1]), "+f"(d[2]), "+f"(d[3])
        : "r"(a[0]), "r"(a[1]), "r"(a[2]), "r"(a[3]), "r"(b0), "r"(b1));
}
static __device__ __forceinline__ uint32_t pkbf(__nv_bfloat16 a, __nv_bfloat16 b) {
    return (uint32_t)__bfloat16_as_ushort(a) |
           ((uint32_t)__bfloat16_as_ushort(b) << 16);
}

/* ----------------------- kernel 1: split W1|W2 -> swizzled bf16 hi/lo in B */
__global__ void k_prep(const float* __restrict__ W1, const float* __restrict__ W2) {
    if (blockIdx.x == 0) {
        for (int i = threadIdx.x; i < BB * OO; i += blockDim.x) g_hmax[i] = 0;
        if (threadIdx.x == 0) g_done = 0;
    }
    const int n = NCH * 2 * 256 * 64;
    for (int i = blockIdx.x * blockDim.x + threadIdx.x; i < n;
         i += gridDim.x * blockDim.x) {
        int k     = i & 63;
        int nr    = (i >> 6) & 255;
        int half  = (i >> 14) & 1;
        int chunk = i >> 15;
        int kc = chunk * 64 + k;
        float w = 0.f;
        if (kc < 4000) {
            int tok = kc >> 3, c = kc & 7;
            const float* W = (nr >= 128) ? W2 : W1;
            int o = nr & 127;
            w = W[o * 4000 + c * 500 + tok];
        }
        __nv_bfloat16 h = __float2bfloat16_rn(w);
        __nv_bfloat16 v = half ? __float2bfloat16_rn(w - __bfloat162float(h)) : h;
        uint32_t byte = (uint32_t)nr * 128 + (uint32_t)k * 2;
        uint32_t base = ((uint32_t)chunk * 2 + half) * 32768;
        g_Bs[(base + SWZ(byte)) >> 1] = v;
    }
}

/* ---------------------------------------------- helpers for main pipeline */
static __device__ __forceinline__ void prefetch_x(const void* xraw, int is64,
                                                  int p0, int t, int chunk,
                                                  int* xi) {
#pragma unroll
    for (int it = 0; it < 4; ++it) {
        const int idx = t + it * 256;
        const int p = idx >> 3, j = idx & 7;
        const int tok = chunk * 8 + j;
        int v = 256;               /* emb[256] is the all-zero pad row */
        if (tok < KER) {
            size_t pos = (size_t)(p0 + p) * KER + tok;
            v = is64 ? (int)__ldg((const long long*)xraw + pos)
                     : __ldg((const int*)xraw + pos);
            v = min(max(v, 0), 256);
        }
        xi[it] = v;
    }
}

static __device__ __forceinline__ void build_A(const float* __restrict__ emb,
                                               const int* xi, int t,
                                               uint32_t AhB, uint32_t AlB) {
#pragma unroll
    for (int it = 0; it < 4; ++it) {
        const int idx = t + it * 256;
        const int p = idx >> 3, j = idx & 7;
        const float4* er = (const float4*)(emb + (size_t)xi[it] * 8);
        float4 ea = __ldg(er), eb = __ldg(er + 1);
        float v[8] = {ea.x, ea.y, ea.z, ea.w, eb.x, eb.y, eb.z, eb.w};
        uint32_t H[4], L[4];
#pragma unroll
        for (int c = 0; c < 4; c++) {
            __nv_bfloat16 h0 = __float2bfloat16_rn(v[2 * c]);
            __nv_bfloat16 h1 = __float2bfloat16_rn(v[2 * c + 1]);
            __nv_bfloat16 l0 = __float2bfloat16_rn(v[2 * c] - __bfloat162float(h0));
            __nv_bfloat16 l1 = __float2bfloat16_rn(v[2 * c + 1] - __bfloat162float(h1));
            H[c] = pkbf(h0, h1); L[c] = pkbf(l0, l1);
        }
        const uint32_t sw = SWZ((uint32_t)p * 128 + (uint32_t)j * 16);
        asm volatile("st.shared.v4.b32 [%0], {%1,%2,%3,%4};"
                     :: "r"(AhB + sw), "r"(H[0]), "r"(H[1]), "r"(H[2]), "r"(H[3])
                     : "memory");
        asm volatile("st.shared.v4.b32 [%0], {%1,%2,%3,%4};"
                     :: "r"(AlB + sw), "r"(L[0]), "r"(L[1]), "r"(L[2]), "r"(L[3])
                     : "memory");
    }
}

static __device__ __forceinline__ void load_B(int chunk, int t, uint32_t Bst) {
    const char* src = (const char*)g_Bs + (size_t)chunk * 65536 + (size_t)t * 16;
    uint32_t dst = Bst + (uint32_t)t * 16;
#pragma unroll
    for (int it = 0; it < 16; ++it)
        asm volatile("cp.async.cg.shared.global [%0], [%1], 16;"
                     :: "r"(dst + it * 4096), "l"(src + (size_t)it * 4096)
                     : "memory");
    asm volatile("cp.async.commit_group;" ::: "memory");
}

/* ------------------------------------------------------ kernel 2: the GEMM */
extern __shared__ char dsm_raw[];

__global__ __launch_bounds__(256, 1)
void k_main(const void* __restrict__ xraw, const float* __restrict__ emb,
            const float* __restrict__ b1, const float* __restrict__ b2,
            const float* __restrict__ fcW, const float* __restrict__ fcb,
            float* __restrict__ out) {
    __shared__ int s_hmax[BB][OO];
    __shared__ int s_flag;
    __shared__ unsigned s_rank;

    const int t = threadIdx.x;
    const int lane = t & 31, wid = t >> 5;
    const int wm = wid & 1, wn = wid >> 1;     /* 2 x 4 warp grid, 64x64 tile */
    const int p0 = blockIdx.x * MT;

    char* dptr = (char*)((((uintptr_t)dsm_raw) + 1023) & ~(uintptr_t)1023);
    const uint32_t dbase = s2u(dptr);

    /* is64 detect (first 512 odd 32-bit words; all-zero iff int64) + init */
    if (t == 0) s_flag = 0;
    for (int i = t; i < BB * OO; i += 256) ((int*)s_hmax)[i] = 0;
    __syncthreads();
    if (((const int*)xraw)[2 * t + 1] | ((const int*)xraw)[2 * (t + 256) + 1])
        s_flag = 1;
    __syncthreads();
    const int is64 = (s_flag == 0);

    /* per-thread ldmatrix row-base byte offsets (within hi/lo blocks) */
    const int lr = lane & 15, seg = lane >> 4;
    uint32_t aRow[4], bRow[4];
#pragma unroll
    for (int mt = 0; mt < 4; ++mt)
        aRow[mt] = (uint32_t)(wm * 64 + mt * 16 + lr) * 128 + seg * 16;
#pragma unroll
    for (int q = 0; q < 4; ++q)
        bRow[q] = (uint32_t)(wn * 64 + q * 16 + lr) * 128 + seg * 16;

    float acc[4][8][4];
#pragma unroll
    for (int a = 0; a < 4; ++a)
#pragma unroll
        for (int b = 0; b < 8; ++b)
#pragma unroll
            for (int c = 0; c < 4; ++c) acc[a][b][c] = 0.f;

    /* preamble: stage 0 */
    int xi[4];
    load_B(0, t, dbase);
    prefetch_x(xraw, is64, p0, t, 0, xi);
    build_A(emb, xi, t, dbase + 65536, dbase + 81920);
    prefetch_x(xraw, is64, p0, t, 1, xi);

    int s = 0;
    for (int i = 0; i < NCH; ++i) {
        asm volatile("cp.async.wait_group 0;" ::: "memory");
        __syncthreads();
        const uint32_t sb = dbase + (uint32_t)s * STAGE_BYTES;
        const uint32_t nb = dbase + (uint32_t)(s ^ 1) * STAGE_BYTES;
        if (i + 1 < NCH) load_B(i + 1, t, nb);

        const uint32_t Bh = sb, Bl = sb + 32768;
        const uint32_t Ah = sb + 65536, Al = sb + 81920;
#pragma unroll
        for (int ks = 0; ks < 4; ++ks) {
            const uint32_t kb = (uint32_t)ks * 32;
            uint32_t fAh[4][4], fAl[4][4];
#pragma unroll
            for (int mt = 0; mt < 4; ++mt) {
                ldsm4(fAh[mt], Ah + SWZ(aRow[mt] + kb));
                ldsm4(fAl[mt], Al + SWZ(aRow[mt] + kb));
            }
#pragma unroll
            for (int q = 0; q < 4; ++q) {
                uint32_t bh[4], bl[4];
                ldsm4(bh, Bh + SWZ(bRow[q] + kb));
                ldsm4(bl, Bl + SWZ(bRow[q] + kb));
                const int nt0 = q * 2;
#pragma unroll
                for (int mt = 0; mt < 4; ++mt) {
                    mma_bf16(acc[mt][nt0], fAh[mt], bh[0], bh[2]);
                    mma_bf16(acc[mt][nt0], fAh[mt], bl[0], bl[2]);
                    mma_bf16(acc[mt][nt0], fAl[mt], bh[0], bh[2]);
                    mma_bf16(acc[mt][nt0 + 1], fAh[mt], bh[1], bh[3]);
                    mma_bf16(acc[mt][nt0 + 1], fAh[mt], bl[1], bl[3]);
                    mma_bf16(acc[mt][nt0 + 1], fAl[mt], bh[1], bh[3]);
                }
            }
        }
        if (i + 1 < NCH) {
            build_A(emb, xi, t, nb + 65536, nb + 81920);
            if (i + 2 < NCH) prefetch_x(xraw, is64, p0, t, i + 2, xi);
        }
        s ^= 1;
    }

    /* --------------------------- epilogue: accums -> smem gbuf[128][256] */
    __syncthreads();
    float* gbuf = (float*)dptr;
    {
        const int r0 = lane >> 2, c0 = (lane & 3) * 2;
#pragma unroll
        for (int mt = 0; mt < 4; ++mt) {
            const int m = wm * 64 + mt * 16;
#pragma unroll
            for (int nt = 0; nt < 8; ++nt) {
                const int n = wn * 64 + nt * 8 + c0;
                gbuf[(m + r0) * 256 + n]     = acc[mt][nt][0];
                gbuf[(m + r0) * 256 + n + 1] = acc[mt][nt][1];
                gbuf[(m + r0 + 8) * 256 + n]     = acc[mt][nt][2];
                gbuf[(m + r0 + 8) * 256 + n + 1] = acc[mt][nt][3];
            }
        }
    }
    __syncthreads();

    /* GLU + per-CTA max */
    {
        const int o = t & 127, pg = t >> 7;
#pragma unroll 8
        for (int j = 0; j < 64; ++j) {
            const int p = pg * 64 + j;
            float g1 = gbuf[p * 256 + o] + __ldg(b1 + o);
            float g2 = gbuf[p * 256 + o + 128] + __ldg(b2 + o);
            float h = fmaxf(g1, 0.f) * (1.f / (1.f + __expf(-g2)));
            const int b = (p0 + p) / 2000;
            atomicMax(&s_hmax[b][o], __float_as_int(h));
        }
    }
    __syncthreads();

    /* flush to global */
    {
        const int blo = p0 / 2000, bhi = (p0 + MT - 1) / 2000;
        const int o = t & 127, which = t >> 7;
        const int b = which ? bhi : blo;
        if (which == 0 || bhi != blo)
            atomicMax(&g_hmax[b * OO + o], s_hmax[b][o]);
    }

    /* last CTA computes the FC head */
    __threadfence();
    __syncthreads();
    if (t == 0) s_rank = atomicAdd(&g_done, 1u);
    __syncthreads();
    if (*(volatile unsigned*)&s_rank == NBLK - 1) {
        __threadfence();
        if (wid == 0) {
#pragma unroll
            for (int pair = 0; pair < 16; ++pair) {
                const int b = pair >> 1, cl = pair & 1;
                float sum = 0.f;
                for (int j = lane; j < OO; j += 32)
                    sum += __ldg(fcW + cl * OO + j) *
                           __int_as_float(g_hmax[b * OO + j]);
#pragma unroll
                for (int off = 16; off; off >>= 1)
                    sum += __shfl_down_sync(0xffffffffu, sum, off);
                if (lane == 0) out[b * 2 + cl] = sum + __ldg(fcb + cl);
            }
        }
    }
}

/* ------------------------------------------------------------------------ */
extern "C" void kernel_launch(void* const* d_in, const int* in_sizes, int n_in,
                              void* d_out, int out_size) {
    const void*  x   = d_in[0];
    const float* emb = (const float*)d_in[1];
    const float* W1  = (const float*)d_in[2];
    const float* b1  = (const float*)d_in[3];
    const float* W2  = (const float*)d_in[4];
    const float* b2  = (const float*)d_in[5];
    const float* fcW = (const float*)d_in[6];
    const float* fcb = (const float*)d_in[7];
    float* out = (float*)d_out;

    cudaFuncSetAttribute(k_main, cudaFuncAttributeMaxDynamicSharedMemorySize,
                         DSMEM);

    k_prep<<<512, 256>>>(W1, W2);
    k_main<<<NBLK, 256, DSMEM>>>(x, emb, b1, b2, fcW, fcb, out);
}